// round 10
// baseline (speedup 1.0000x reference)
#include <cuda_runtime.h>
#include <cuda_bf16.h>
#include <cstdint>

#define NN 8192
#define DD 512
#define INV_T 25.0f
#define EPS_KOLEO 1e-9f

// ------------------- device scratch -------------------
__device__ __nv_bfloat16 g_zb1[NN * DD];
__device__ __nv_bfloat16 g_zb2[NN * DD];
__device__ float g_rowsum[NN];
__device__ float g_colsum[NN];
__device__ float g_diag[NN];
__device__ int   g_max1[NN];
__device__ int   g_max2[NN];

// ------------------- helpers -------------------
__device__ __forceinline__ int enc_f(float f) {
    int i = __float_as_int(f);
    return i >= 0 ? i : i ^ 0x7FFFFFFF;
}
__device__ __forceinline__ float dec_f(int i) {
    return __int_as_float(i >= 0 ? i : i ^ 0x7FFFFFFF);
}
__device__ __forceinline__ uint32_t smem_u32(const void* p) {
    uint32_t a;
    asm("{ .reg .u64 t; cvta.to.shared.u64 t, %1; cvt.u32.u64 %0, t; }"
        : "=r"(a) : "l"(p));
    return a;
}
__device__ __forceinline__ void cp16(uint32_t saddr, const void* g) {
    asm volatile("cp.async.cg.shared.global [%0], [%1], 16;" :: "r"(saddr), "l"(g));
}
__device__ __forceinline__ void cp_commit() {
    asm volatile("cp.async.commit_group;" ::: "memory");
}
__device__ __forceinline__ void cp_wait1() {
    asm volatile("cp.async.wait_group 1;" ::: "memory");
}
__device__ __forceinline__ void cp_wait0() {
    asm volatile("cp.async.wait_group 0;" ::: "memory");
}
__device__ __forceinline__ void ldsm_x4(uint32_t* r, uint32_t a) {
    asm volatile("ldmatrix.sync.aligned.m8n8.x4.shared.b16 {%0,%1,%2,%3}, [%4];"
                 : "=r"(r[0]), "=r"(r[1]), "=r"(r[2]), "=r"(r[3]) : "r"(a));
}
__device__ __forceinline__ void mma_bf16(float* c, const uint32_t* a, const uint32_t* b) {
    asm volatile(
        "mma.sync.aligned.m16n8k16.row.col.f32.bf16.bf16.f32 "
        "{%0,%1,%2,%3}, {%4,%5,%6,%7}, {%8,%9}, {%0,%1,%2,%3};"
        : "+f"(c[0]), "+f"(c[1]), "+f"(c[2]), "+f"(c[3])
        : "r"(a[0]), "r"(a[1]), "r"(a[2]), "r"(a[3]), "r"(b[0]), "r"(b[1]));
}

// ------------- normalization (both matrices) + scalar init -------------
__global__ void normalize_kernel(const float* __restrict__ z1,
                                 const float* __restrict__ z2) {
    int row = blockIdx.x;
    int t = threadIdx.x;  // 128 threads x 4 floats per matrix
    float4 v1 = ((const float4*)(z1 + (size_t)row * DD))[t];
    float4 v2 = ((const float4*)(z2 + (size_t)row * DD))[t];
    float s1 = v1.x * v1.x + v1.y * v1.y + v1.z * v1.z + v1.w * v1.w;
    float s2 = v2.x * v2.x + v2.y * v2.y + v2.z * v2.z + v2.w * v2.w;
#pragma unroll
    for (int o = 16; o; o >>= 1) {
        s1 += __shfl_xor_sync(0xffffffffu, s1, o);
        s2 += __shfl_xor_sync(0xffffffffu, s2, o);
    }
    __shared__ float ws[2][4];
    if ((t & 31) == 0) {
        ws[0][t >> 5] = s1;
        ws[1][t >> 5] = s2;
    }
    __syncthreads();
    float t1 = ws[0][0] + ws[0][1] + ws[0][2] + ws[0][3];
    float t2 = ws[1][0] + ws[1][1] + ws[1][2] + ws[1][3];
    float sc1 = 1.0f / fmaxf(sqrtf(t1), 1e-12f);
    float sc2 = 1.0f / fmaxf(sqrtf(t2), 1e-12f);
    __nv_bfloat162* d1 = (__nv_bfloat162*)(g_zb1 + (size_t)row * DD);
    __nv_bfloat162* d2 = (__nv_bfloat162*)(g_zb2 + (size_t)row * DD);
    d1[t * 2 + 0] = __floats2bfloat162_rn(v1.x * sc1, v1.y * sc1);
    d1[t * 2 + 1] = __floats2bfloat162_rn(v1.z * sc1, v1.w * sc1);
    d2[t * 2 + 0] = __floats2bfloat162_rn(v2.x * sc2, v2.y * sc2);
    d2[t * 2 + 1] = __floats2bfloat162_rn(v2.z * sc2, v2.w * sc2);
    if (t == 0) {
        g_rowsum[row] = 0.0f;
        g_colsum[row] = 0.0f;
        g_diag[row] = 0.0f;
        int e = enc_f(-2.0f);
        g_max1[row] = e;
        g_max2[row] = e;
    }
}

// =====================================================================
// Fused HMMA GEMM, exact 1D grid:
//   t in [0,4096):      mode 0 cross, bi = t>>6, bj = t&63
//   t in [4096,6176):   mode 1 gram z1 (triangle decode)
//   t in [6176,8256):   mode 2 gram z2
// CTA tile 128x128, 4 warps (2x2), warp tile 64x64, BK=64, 8 chunks,
// 3-stage cp.async, one __syncthreads per chunk. 2 CTAs / SM.
// smem row: 128B data @ 144B pitch (36 banks/row => conflict-free ldsm)
// =====================================================================
#define PITCH 144
#define ST_A  (128 * PITCH)              // 18432
#define STAGE (2 * ST_A)                 // 36864 (A + B)
#define SMEM_DYN (3 * STAGE)             // 110592
#define NTRI  2080                       // 64*65/2

__global__ __launch_bounds__(128, 2) void gemm_all() {
    int mode, bi, bj;
    {
        int t = blockIdx.x;
        if (t < 4096) {
            mode = 0; bi = t >> 6; bj = t & 63;
        } else {
            int u = t - 4096;
            mode = 1;
            if (u >= NTRI) { mode = 2; u -= NTRI; }
            int b = (int)((sqrtf((float)(8 * u + 1)) - 1.0f) * 0.5f);
            while ((b + 1) * (b + 2) / 2 <= u) b++;
            while (b * (b + 1) / 2 > u) b--;
            bi = b;
            bj = u - b * (b + 1) / 2;
        }
    }
    const bool hasDiag = (bi == bj);

    extern __shared__ __align__(16) char smem[];
    __shared__ int sred[256];            // [0:128) rows, [128:256) cols

    const int tid = threadIdx.x;         // 128
    const int wid = tid >> 5;            // 0..3
    const int lane = tid & 31;
    const int wm = (wid >> 1) * 64;
    const int wn = (wid & 1) * 64;

    const __nv_bfloat16* __restrict__ A = (mode == 2) ? g_zb2 : g_zb1;
    const __nv_bfloat16* __restrict__ B = (mode == 1) ? g_zb1 : g_zb2;

    const size_t arow0 = (size_t)bi * 128;
    const size_t brow0 = (size_t)bj * 128;

    const uint32_t sdyn = smem_u32(smem);

    // loader: per BK=64 chunk, A: 128 rows x 8 x 16B, B same.
    const int ldrow = tid >> 3;          // 0..15 base (8 iters cover 128)
    const int ldseg = tid & 7;
    auto load_chunk = [&](int kc, int s) {
        uint32_t base = sdyn + s * STAGE;
#pragma unroll
        for (int it = 0; it < 8; it++) {
            int row = ldrow + it * 16;
            uint32_t off = row * PITCH + ldseg * 16;
            cp16(base + off, A + (arow0 + row) * DD + kc * 64 + ldseg * 8);
            cp16(base + ST_A + off, B + (brow0 + row) * DD + kc * 64 + ldseg * 8);
        }
        cp_commit();
    };

    float acc[4][8][4];
#pragma unroll
    for (int mi = 0; mi < 4; mi++)
#pragma unroll
        for (int ni = 0; ni < 8; ni++)
#pragma unroll
            for (int q = 0; q < 4; q++) acc[mi][ni][q] = 0.0f;

    load_chunk(0, 0);
    load_chunk(1, 1);

    const uint32_t aOff = (wm + (lane & 15)) * PITCH + (lane >> 4) * 16;
    const uint32_t bOff = ST_A +
        (wn + (lane & 7) + ((lane >> 4) & 1) * 8) * PITCH + ((lane >> 3) & 1) * 16;

    int s = 0;
    for (int i = 0; i < 8; i++) {
        if (i < 7) cp_wait1(); else cp_wait0();
        __syncthreads();
        if (i + 2 < 8) {
            int sn = s + 2; if (sn >= 3) sn -= 3;
            load_chunk(i + 2, sn);
        }
        uint32_t stg = sdyn + s * STAGE;
        uint32_t aBase = stg + aOff;
        uint32_t bBase = stg + bOff;
#pragma unroll
        for (int k16 = 0; k16 < 4; k16++) {
            uint32_t a[4][4], b[8][2];
#pragma unroll
            for (int mi = 0; mi < 4; mi++)
                ldsm_x4(a[mi], aBase + mi * 16 * PITCH + k16 * 32);
#pragma unroll
            for (int nq = 0; nq < 4; nq++) {
                uint32_t t[4];
                ldsm_x4(t, bBase + nq * 16 * PITCH + k16 * 32);
                b[2 * nq][0] = t[0]; b[2 * nq][1] = t[1];
                b[2 * nq + 1][0] = t[2]; b[2 * nq + 1][1] = t[3];
            }
#pragma unroll
            for (int mi = 0; mi < 4; mi++)
#pragma unroll
                for (int ni = 0; ni < 8; ni++)
                    mma_bf16(acc[mi][ni], a[mi], b[ni]);
        }
        s++; if (s >= 3) s -= 3;
    }

    // ---------------- epilogue ----------------
    const int g = lane >> 2;
    const int t4 = lane & 3;

    if (mode == 0) {
        float* sf = (float*)sred;
        sf[tid] = 0.0f;
        sf[128 + tid] = 0.0f;
        __syncthreads();

        float colacc[8][2];
#pragma unroll
        for (int ni = 0; ni < 8; ni++) { colacc[ni][0] = 0.0f; colacc[ni][1] = 0.0f; }

#pragma unroll
        for (int mi = 0; mi < 4; mi++) {
            int gr0 = bi * 128 + wm + mi * 16 + g;
            int gr1 = gr0 + 8;
            float row0 = 0.0f, row1 = 0.0f;
#pragma unroll
            for (int ni = 0; ni < 8; ni++) {
                float l00 = acc[mi][ni][0] * INV_T;
                float l01 = acc[mi][ni][1] * INV_T;
                float l10 = acc[mi][ni][2] * INV_T;
                float l11 = acc[mi][ni][3] * INV_T;
                if (hasDiag) {
                    int gc0 = bj * 128 + wn + ni * 8 + t4 * 2;
                    if (gr0 == gc0)     g_diag[gr0] = l00;
                    if (gr0 == gc0 + 1) g_diag[gr0] = l01;
                    if (gr1 == gc0)     g_diag[gr1] = l10;
                    if (gr1 == gc0 + 1) g_diag[gr1] = l11;
                }
                float e00 = __expf(l00), e01 = __expf(l01);
                float e10 = __expf(l10), e11 = __expf(l11);
                row0 += e00 + e01;
                row1 += e10 + e11;
                colacc[ni][0] += e00 + e10;
                colacc[ni][1] += e01 + e11;
            }
            row0 += __shfl_xor_sync(0xffffffffu, row0, 1);
            row0 += __shfl_xor_sync(0xffffffffu, row0, 2);
            row1 += __shfl_xor_sync(0xffffffffu, row1, 1);
            row1 += __shfl_xor_sync(0xffffffffu, row1, 2);
            if (t4 == 0) {
                atomicAdd(&sf[wm + mi * 16 + g], row0);
                atomicAdd(&sf[wm + mi * 16 + g + 8], row1);
            }
        }
#pragma unroll
        for (int ni = 0; ni < 8; ni++) {
#pragma unroll
            for (int j = 0; j < 2; j++) {
                float v = colacc[ni][j];
                v += __shfl_xor_sync(0xffffffffu, v, 4);
                v += __shfl_xor_sync(0xffffffffu, v, 8);
                v += __shfl_xor_sync(0xffffffffu, v, 16);
                if (lane < 4)
                    atomicAdd(&sf[128 + wn + ni * 8 + (lane & 3) * 2 + j], v);
            }
        }
        __syncthreads();
        atomicAdd(&g_rowsum[bi * 128 + tid], sf[tid]);
        atomicAdd(&g_colsum[bj * 128 + tid], sf[128 + tid]);
    } else {
        int* __restrict__ mx = (mode == 1) ? g_max1 : g_max2;
        const int encneg = enc_f(-2.0f);
        sred[tid] = encneg;
        sred[128 + tid] = encneg;
        __syncthreads();

        float colm[8][2];
#pragma unroll
        for (int ni = 0; ni < 8; ni++) { colm[ni][0] = -2.0f; colm[ni][1] = -2.0f; }

#pragma unroll
        for (int mi = 0; mi < 4; mi++) {
            int gr0 = bi * 128 + wm + mi * 16 + g;
            int gr1 = gr0 + 8;
            float row0 = -2.0f, row1 = -2.0f;
#pragma unroll
            for (int ni = 0; ni < 8; ni++) {
                float v00 = acc[mi][ni][0];
                float v01 = acc[mi][ni][1];
                float v10 = acc[mi][ni][2];
                float v11 = acc[mi][ni][3];
                if (hasDiag) {
                    int gc0 = bj * 128 + wn + ni * 8 + t4 * 2;
                    if (gr0 == gc0)     v00 = -2.0f;
                    if (gr0 == gc0 + 1) v01 = -2.0f;
                    if (gr1 == gc0)     v10 = -2.0f;
                    if (gr1 == gc0 + 1) v11 = -2.0f;
                }
                row0 = fmaxf(row0, fmaxf(v00, v01));
                row1 = fmaxf(row1, fmaxf(v10, v11));
                colm[ni][0] = fmaxf(colm[ni][0], fmaxf(v00, v10));
                colm[ni][1] = fmaxf(colm[ni][1], fmaxf(v01, v11));
            }
            row0 = fmaxf(row0, __shfl_xor_sync(0xffffffffu, row0, 1));
            row0 = fmaxf(row0, __shfl_xor_sync(0xffffffffu, row0, 2));
            row1 = fmaxf(row1, __shfl_xor_sync(0xffffffffu, row1, 1));
            row1 = fmaxf(row1, __shfl_xor_sync(0xffffffffu, row1, 2));
            if (t4 == 0) {
                atomicMax(&sred[wm + mi * 16 + g], enc_f(row0));
                atomicMax(&sred[wm + mi * 16 + g + 8], enc_f(row1));
            }
        }
#pragma unroll
        for (int ni = 0; ni < 8; ni++) {
#pragma unroll
            for (int j = 0; j < 2; j++) {
                float v = colm[ni][j];
                v = fmaxf(v, __shfl_xor_sync(0xffffffffu, v, 4));
                v = fmaxf(v, __shfl_xor_sync(0xffffffffu, v, 8));
                v = fmaxf(v, __shfl_xor_sync(0xffffffffu, v, 16));
                if (lane < 4)
                    atomicMax(&sred[128 + wn + ni * 8 + (lane & 3) * 2 + j], enc_f(v));
            }
        }
        __syncthreads();
        atomicMax(&mx[bi * 128 + tid], sred[tid]);
        atomicMax(&mx[bj * 128 + tid], sred[128 + tid]);
    }
}

// ------------------- final scalar reduction (1024 threads) -------------------
__global__ void finalize_kernel(float* __restrict__ out) {
    const int t = threadIdx.x;  // 1024
    float s12 = 0.0f, s21 = 0.0f, k1 = 0.0f, k2 = 0.0f;
#pragma unroll
    for (int it = 0; it < NN / 1024; it++) {
        int i = t + it * 1024;
        float d = g_diag[i];
        s12 += __logf(g_rowsum[i]) - d;
        s21 += __logf(g_colsum[i]) - d;
        float m1 = dec_f(g_max1[i]);
        float m2 = dec_f(g_max2[i]);
        float d1 = sqrtf(fmaxf(2.0f - 2.0f * m1, 0.0f));
        float d2 = sqrtf(fmaxf(2.0f - 2.0f * m2, 0.0f));
        k1 += __logf(d1 + EPS_KOLEO);
        k2 += __logf(d2 + EPS_KOLEO);
    }
    float vals[4] = {s12, s21, k1, k2};
    __shared__ float sh[4][32];
#pragma unroll
    for (int q = 0; q < 4; q++) {
        float v = vals[q];
#pragma unroll
        for (int o = 16; o; o >>= 1) v += __shfl_xor_sync(0xffffffffu, v, o);
        if ((t & 31) == 0) sh[q][t >> 5] = v;
    }
    __syncthreads();
    if (t < 32) {
        float r[4];
#pragma unroll
        for (int q = 0; q < 4; q++) {
            float v = sh[q][t];
#pragma unroll
            for (int o = 16; o; o >>= 1) v += __shfl_xor_sync(0xffffffffu, v, o);
            r[q] = v;
        }
        if (t == 0) {
            float contrast = (r[0] + r[1]) / (2.0f * NN);
            float koleo = -(r[2] + r[3]) / (2.0f * NN);
            out[0] = contrast + 0.1f * koleo;
        }
    }
}

// ------------------- launch -------------------
extern "C" void kernel_launch(void* const* d_in, const int* in_sizes, int n_in,
                              void* d_out, int out_size) {
    const float* z1 = (const float*)d_in[0];
    const float* z2 = (const float*)d_in[1];
    float* out = (float*)d_out;

    cudaFuncSetAttribute(gemm_all, cudaFuncAttributeMaxDynamicSharedMemorySize,
                         SMEM_DYN);

    normalize_kernel<<<NN, 128>>>(z1, z2);
    gemm_all<<<4096 + 2 * NTRI, 128, SMEM_DYN>>>();
    finalize_kernel<<<1, 1024>>>(out);
}

// round 11
// speedup vs baseline: 1.5037x; 1.5037x over previous
#include <cuda_runtime.h>
#include <cuda_bf16.h>
#include <cstdint>

#define NN 8192
#define DD 512
#define INV_T 25.0f
#define EPS_KOLEO 1e-9f

// ------------------- device scratch -------------------
__device__ __nv_bfloat16 g_zb1[NN * DD];
__device__ __nv_bfloat16 g_zb2[NN * DD];
__device__ float g_rowsum[NN];
__device__ float g_colsum[NN];
__device__ float g_diag[NN];
__device__ int   g_max1[NN];
__device__ int   g_max2[NN];

// ------------------- helpers -------------------
__device__ __forceinline__ int enc_f(float f) {
    int i = __float_as_int(f);
    return i >= 0 ? i : i ^ 0x7FFFFFFF;
}
__device__ __forceinline__ float dec_f(int i) {
    return __int_as_float(i >= 0 ? i : i ^ 0x7FFFFFFF);
}
__device__ __forceinline__ uint32_t smem_u32(const void* p) {
    uint32_t a;
    asm("{ .reg .u64 t; cvta.to.shared.u64 t, %1; cvt.u32.u64 %0, t; }"
        : "=r"(a) : "l"(p));
    return a;
}
__device__ __forceinline__ void cp16(uint32_t saddr, const void* g) {
    asm volatile("cp.async.cg.shared.global [%0], [%1], 16;" :: "r"(saddr), "l"(g));
}
__device__ __forceinline__ void cp_commit() {
    asm volatile("cp.async.commit_group;" ::: "memory");
}
__device__ __forceinline__ void cp_wait0() {
    asm volatile("cp.async.wait_group 0;" ::: "memory");
}
__device__ __forceinline__ void ldsm_x4(uint32_t* r, uint32_t a) {
    asm volatile("ldmatrix.sync.aligned.m8n8.x4.shared.b16 {%0,%1,%2,%3}, [%4];"
                 : "=r"(r[0]), "=r"(r[1]), "=r"(r[2]), "=r"(r[3]) : "r"(a));
}
__device__ __forceinline__ void mma_bf16(float* c, const uint32_t* a, const uint32_t* b) {
    asm volatile(
        "mma.sync.aligned.m16n8k16.row.col.f32.bf16.bf16.f32 "
        "{%0,%1,%2,%3}, {%4,%5,%6,%7}, {%8,%9}, {%0,%1,%2,%3};"
        : "+f"(c[0]), "+f"(c[1]), "+f"(c[2]), "+f"(c[3])
        : "r"(a[0]), "r"(a[1]), "r"(a[2]), "r"(a[3]), "r"(b[0]), "r"(b[1]));
}

// ------------- normalization (both matrices) + scalar init -------------
__global__ void normalize_kernel(const float* __restrict__ z1,
                                 const float* __restrict__ z2) {
    int row = blockIdx.x;
    int t = threadIdx.x;  // 128 threads x 4 floats per matrix
    float4 v1 = ((const float4*)(z1 + (size_t)row * DD))[t];
    float4 v2 = ((const float4*)(z2 + (size_t)row * DD))[t];
    float s1 = v1.x * v1.x + v1.y * v1.y + v1.z * v1.z + v1.w * v1.w;
    float s2 = v2.x * v2.x + v2.y * v2.y + v2.z * v2.z + v2.w * v2.w;
#pragma unroll
    for (int o = 16; o; o >>= 1) {
        s1 += __shfl_xor_sync(0xffffffffu, s1, o);
        s2 += __shfl_xor_sync(0xffffffffu, s2, o);
    }
    __shared__ float ws[2][4];
    if ((t & 31) == 0) {
        ws[0][t >> 5] = s1;
        ws[1][t >> 5] = s2;
    }
    __syncthreads();
    float t1 = ws[0][0] + ws[0][1] + ws[0][2] + ws[0][3];
    float t2 = ws[1][0] + ws[1][1] + ws[1][2] + ws[1][3];
    float sc1 = 1.0f / fmaxf(sqrtf(t1), 1e-12f);
    float sc2 = 1.0f / fmaxf(sqrtf(t2), 1e-12f);
    __nv_bfloat162* d1 = (__nv_bfloat162*)(g_zb1 + (size_t)row * DD);
    __nv_bfloat162* d2 = (__nv_bfloat162*)(g_zb2 + (size_t)row * DD);
    d1[t * 2 + 0] = __floats2bfloat162_rn(v1.x * sc1, v1.y * sc1);
    d1[t * 2 + 1] = __floats2bfloat162_rn(v1.z * sc1, v1.w * sc1);
    d2[t * 2 + 0] = __floats2bfloat162_rn(v2.x * sc2, v2.y * sc2);
    d2[t * 2 + 1] = __floats2bfloat162_rn(v2.z * sc2, v2.w * sc2);
    if (t == 0) {
        g_rowsum[row] = 0.0f;
        g_colsum[row] = 0.0f;
        g_diag[row] = 0.0f;
        int e = enc_f(-2.0f);
        g_max1[row] = e;
        g_max2[row] = e;
    }
}

// =====================================================================
// Fused HMMA GEMM, exact 1D grid:
//   t in [0,4096):      mode 0 cross, bi = t>>6, bj = t&63
//   t in [4096,6176):   mode 1 gram z1 (triangle decode)
//   t in [6176,8256):   mode 2 gram z2
// CTA tile 128x128, 4 warps (2x2), warp tile 64x64, BK=64, 8 chunks,
// 2-stage double buffer (depth-1 prefetch), one __syncthreads per chunk.
// SMEM 72KB/CTA -> 2 CTAs/SM (147KB of 228KB).
// smem row: 128B data @ 144B pitch (36 banks/row => conflict-free ldsm)
// =====================================================================
#define PITCH 144
#define ST_A  (128 * PITCH)              // 18432
#define STAGE (2 * ST_A)                 // 36864 (A + B)
#define SMEM_DYN (2 * STAGE)             // 73728
#define NTRI  2080                       // 64*65/2

__global__ __launch_bounds__(128, 2) void gemm_all() {
    int mode, bi, bj;
    {
        int t = blockIdx.x;
        if (t < 4096) {
            mode = 0; bi = t >> 6; bj = t & 63;
        } else {
            int u = t - 4096;
            mode = 1;
            if (u >= NTRI) { mode = 2; u -= NTRI; }
            int b = (int)((sqrtf((float)(8 * u + 1)) - 1.0f) * 0.5f);
            while ((b + 1) * (b + 2) / 2 <= u) b++;
            while (b * (b + 1) / 2 > u) b--;
            bi = b;
            bj = u - b * (b + 1) / 2;
        }
    }
    const bool hasDiag = (bi == bj);

    extern __shared__ __align__(16) char smem[];
    __shared__ int sred[256];            // [0:128) rows, [128:256) cols

    const int tid = threadIdx.x;         // 128
    const int wid = tid >> 5;            // 0..3
    const int lane = tid & 31;
    const int wm = (wid >> 1) * 64;
    const int wn = (wid & 1) * 64;

    const __nv_bfloat16* __restrict__ A = (mode == 2) ? g_zb2 : g_zb1;
    const __nv_bfloat16* __restrict__ B = (mode == 1) ? g_zb1 : g_zb2;

    const size_t arow0 = (size_t)bi * 128;
    const size_t brow0 = (size_t)bj * 128;

    const uint32_t sdyn = smem_u32(smem);

    // loader: per BK=64 chunk, A: 128 rows x 8 x 16B, B same.
    const int ldrow = tid >> 3;          // 0..15 base (8 iters cover 128)
    const int ldseg = tid & 7;
    auto load_chunk = [&](int kc, int s) {
        uint32_t base = sdyn + s * STAGE;
#pragma unroll
        for (int it = 0; it < 8; it++) {
            int row = ldrow + it * 16;
            uint32_t off = row * PITCH + ldseg * 16;
            cp16(base + off, A + (arow0 + row) * DD + kc * 64 + ldseg * 8);
            cp16(base + ST_A + off, B + (brow0 + row) * DD + kc * 64 + ldseg * 8);
        }
        cp_commit();
    };

    float acc[4][8][4];
#pragma unroll
    for (int mi = 0; mi < 4; mi++)
#pragma unroll
        for (int ni = 0; ni < 8; ni++)
#pragma unroll
            for (int q = 0; q < 4; q++) acc[mi][ni][q] = 0.0f;

    load_chunk(0, 0);

    const uint32_t aOff = (wm + (lane & 15)) * PITCH + (lane >> 4) * 16;
    const uint32_t bOff = ST_A +
        (wn + (lane & 7) + ((lane >> 4) & 1) * 8) * PITCH + ((lane >> 3) & 1) * 16;

    for (int i = 0; i < 8; i++) {
        cp_wait0();                      // chunk i arrived (only group in flight)
        __syncthreads();                 // + buffer (i+1)&1's old readers done
        if (i + 1 < 8) load_chunk(i + 1, (i + 1) & 1);

        uint32_t stg = sdyn + (i & 1) * STAGE;
        uint32_t aBase = stg + aOff;
        uint32_t bBase = stg + bOff;
#pragma unroll
        for (int k16 = 0; k16 < 4; k16++) {
            uint32_t a[4][4], b[8][2];
#pragma unroll
            for (int mi = 0; mi < 4; mi++)
                ldsm_x4(a[mi], aBase + mi * 16 * PITCH + k16 * 32);
#pragma unroll
            for (int nq = 0; nq < 4; nq++) {
                uint32_t t[4];
                ldsm_x4(t, bBase + nq * 16 * PITCH + k16 * 32);
                b[2 * nq][0] = t[0]; b[2 * nq][1] = t[1];
                b[2 * nq + 1][0] = t[2]; b[2 * nq + 1][1] = t[3];
            }
#pragma unroll
            for (int mi = 0; mi < 4; mi++)
#pragma unroll
                for (int ni = 0; ni < 8; ni++)
                    mma_bf16(acc[mi][ni], a[mi], b[ni]);
        }
    }

    // ---------------- epilogue ----------------
    const int g = lane >> 2;
    const int t4 = lane & 3;

    if (mode == 0) {
        float* sf = (float*)sred;
        sf[tid] = 0.0f;
        sf[128 + tid] = 0.0f;
        __syncthreads();

        float colacc[8][2];
#pragma unroll
        for (int ni = 0; ni < 8; ni++) { colacc[ni][0] = 0.0f; colacc[ni][1] = 0.0f; }

#pragma unroll
        for (int mi = 0; mi < 4; mi++) {
            int gr0 = bi * 128 + wm + mi * 16 + g;
            int gr1 = gr0 + 8;
            float row0 = 0.0f, row1 = 0.0f;
#pragma unroll
            for (int ni = 0; ni < 8; ni++) {
                float l00 = acc[mi][ni][0] * INV_T;
                float l01 = acc[mi][ni][1] * INV_T;
                float l10 = acc[mi][ni][2] * INV_T;
                float l11 = acc[mi][ni][3] * INV_T;
                if (hasDiag) {
                    int gc0 = bj * 128 + wn + ni * 8 + t4 * 2;
                    if (gr0 == gc0)     g_diag[gr0] = l00;
                    if (gr0 == gc0 + 1) g_diag[gr0] = l01;
                    if (gr1 == gc0)     g_diag[gr1] = l10;
                    if (gr1 == gc0 + 1) g_diag[gr1] = l11;
                }
                float e00 = __expf(l00), e01 = __expf(l01);
                float e10 = __expf(l10), e11 = __expf(l11);
                row0 += e00 + e01;
                row1 += e10 + e11;
                colacc[ni][0] += e00 + e10;
                colacc[ni][1] += e01 + e11;
            }
            row0 += __shfl_xor_sync(0xffffffffu, row0, 1);
            row0 += __shfl_xor_sync(0xffffffffu, row0, 2);
            row1 += __shfl_xor_sync(0xffffffffu, row1, 1);
            row1 += __shfl_xor_sync(0xffffffffu, row1, 2);
            if (t4 == 0) {
                atomicAdd(&sf[wm + mi * 16 + g], row0);
                atomicAdd(&sf[wm + mi * 16 + g + 8], row1);
            }
        }
#pragma unroll
        for (int ni = 0; ni < 8; ni++) {
#pragma unroll
            for (int j = 0; j < 2; j++) {
                float v = colacc[ni][j];
                v += __shfl_xor_sync(0xffffffffu, v, 4);
                v += __shfl_xor_sync(0xffffffffu, v, 8);
                v += __shfl_xor_sync(0xffffffffu, v, 16);
                if (lane < 4)
                    atomicAdd(&sf[128 + wn + ni * 8 + (lane & 3) * 2 + j], v);
            }
        }
        __syncthreads();
        atomicAdd(&g_rowsum[bi * 128 + tid], sf[tid]);
        atomicAdd(&g_colsum[bj * 128 + tid], sf[128 + tid]);
    } else {
        int* __restrict__ mx = (mode == 1) ? g_max1 : g_max2;
        const int encneg = enc_f(-2.0f);
        sred[tid] = encneg;
        sred[128 + tid] = encneg;
        __syncthreads();

        float colm[8][2];
#pragma unroll
        for (int ni = 0; ni < 8; ni++) { colm[ni][0] = -2.0f; colm[ni][1] = -2.0f; }

#pragma unroll
        for (int mi = 0; mi < 4; mi++) {
            int gr0 = bi * 128 + wm + mi * 16 + g;
            int gr1 = gr0 + 8;
            float row0 = -2.0f, row1 = -2.0f;
#pragma unroll
            for (int ni = 0; ni < 8; ni++) {
                float v00 = acc[mi][ni][0];
                float v01 = acc[mi][ni][1];
                float v10 = acc[mi][ni][2];
                float v11 = acc[mi][ni][3];
                if (hasDiag) {
                    int gc0 = bj * 128 + wn + ni * 8 + t4 * 2;
                    if (gr0 == gc0)     v00 = -2.0f;
                    if (gr0 == gc0 + 1) v01 = -2.0f;
                    if (gr1 == gc0)     v10 = -2.0f;
                    if (gr1 == gc0 + 1) v11 = -2.0f;
                }
                row0 = fmaxf(row0, fmaxf(v00, v01));
                row1 = fmaxf(row1, fmaxf(v10, v11));
                colm[ni][0] = fmaxf(colm[ni][0], fmaxf(v00, v10));
                colm[ni][1] = fmaxf(colm[ni][1], fmaxf(v01, v11));
            }
            row0 = fmaxf(row0, __shfl_xor_sync(0xffffffffu, row0, 1));
            row0 = fmaxf(row0, __shfl_xor_sync(0xffffffffu, row0, 2));
            row1 = fmaxf(row1, __shfl_xor_sync(0xffffffffu, row1, 1));
            row1 = fmaxf(row1, __shfl_xor_sync(0xffffffffu, row1, 2));
            if (t4 == 0) {
                atomicMax(&sred[wm + mi * 16 + g], enc_f(row0));
                atomicMax(&sred[wm + mi * 16 + g + 8], enc_f(row1));
            }
        }
#pragma unroll
        for (int ni = 0; ni < 8; ni++) {
#pragma unroll
            for (int j = 0; j < 2; j++) {
                float v = colm[ni][j];
                v = fmaxf(v, __shfl_xor_sync(0xffffffffu, v, 4));
                v = fmaxf(v, __shfl_xor_sync(0xffffffffu, v, 8));
                v = fmaxf(v, __shfl_xor_sync(0xffffffffu, v, 16));
                if (lane < 4)
                    atomicMax(&sred[128 + wn + ni * 8 + (lane & 3) * 2 + j], enc_f(v));
            }
        }
        __syncthreads();
        atomicMax(&mx[bi * 128 + tid], sred[tid]);
        atomicMax(&mx[bj * 128 + tid], sred[128 + tid]);
    }
}

// ------------------- final scalar reduction (1024 threads) -------------------
__global__ void finalize_kernel(float* __restrict__ out) {
    const int t = threadIdx.x;  // 1024
    float s12 = 0.0f, s21 = 0.0f, k1 = 0.0f, k2 = 0.0f;
#pragma unroll
    for (int it = 0; it < NN / 1024; it++) {
        int i = t + it * 1024;
        float d = g_diag[i];
        s12 += __logf(g_rowsum[i]) - d;
        s21 += __logf(g_colsum[i]) - d;
        float m1 = dec_f(g_max1[i]);
        float m2 = dec_f(g_max2[i]);
        float d1 = sqrtf(fmaxf(2.0f - 2.0f * m1, 0.0f));
        float d2 = sqrtf(fmaxf(2.0f - 2.0f * m2, 0.0f));
        k1 += __logf(d1 + EPS_KOLEO);
        k2 += __logf(d2 + EPS_KOLEO);
    }
    float vals[4] = {s12, s21, k1, k2};
    __shared__ float sh[4][32];
#pragma unroll
    for (int q = 0; q < 4; q++) {
        float v = vals[q];
#pragma unroll
        for (int o = 16; o; o >>= 1) v += __shfl_xor_sync(0xffffffffu, v, o);
        if ((t & 31) == 0) sh[q][t >> 5] = v;
    }
    __syncthreads();
    if (t < 32) {
        float r[4];
#pragma unroll
        for (int q = 0; q < 4; q++) {
            float v = sh[q][t];
#pragma unroll
            for (int o = 16; o; o >>= 1) v += __shfl_xor_sync(0xffffffffu, v, o);
            r[q] = v;
        }
        if (t == 0) {
            float contrast = (r[0] + r[1]) / (2.0f * NN);
            float koleo = -(r[2] + r[3]) / (2.0f * NN);
            out[0] = contrast + 0.1f * koleo;
        }
    }
}

// ------------------- launch -------------------
extern "C" void kernel_launch(void* const* d_in, const int* in_sizes, int n_in,
                              void* d_out, int out_size) {
    const float* z1 = (const float*)d_in[0];
    const float* z2 = (const float*)d_in[1];
    float* out = (float*)d_out;

    cudaFuncSetAttribute(gemm_all, cudaFuncAttributeMaxDynamicSharedMemorySize,
                         SMEM_DYN);

    normalize_kernel<<<NN, 128>>>(z1, z2);
    gemm_all<<<4096 + 2 * NTRI, 128, SMEM_DYN>>>();
    finalize_kernel<<<1, 1024>>>(out);
}

// round 12
// speedup vs baseline: 1.5057x; 1.0013x over previous
#include <cuda_runtime.h>
#include <cuda_bf16.h>
#include <cstdint>

#define NN 8192
#define DD 512
#define INV_T 25.0f
#define EPS_KOLEO 1e-9f

// ------------------- device scratch -------------------
__device__ __nv_bfloat16 g_zb1[NN * DD];
__device__ __nv_bfloat16 g_zb2[NN * DD];
__device__ float g_rowsum[NN];
__device__ float g_colsum[NN];
__device__ float g_diag[NN];
__device__ int   g_max1[NN];
__device__ int   g_max2[NN];

// ------------------- helpers -------------------
__device__ __forceinline__ int enc_f(float f) {
    int i = __float_as_int(f);
    return i >= 0 ? i : i ^ 0x7FFFFFFF;
}
__device__ __forceinline__ float dec_f(int i) {
    return __int_as_float(i >= 0 ? i : i ^ 0x7FFFFFFF);
}
__device__ __forceinline__ uint32_t smem_u32(const void* p) {
    uint32_t a;
    asm("{ .reg .u64 t; cvta.to.shared.u64 t, %1; cvt.u32.u64 %0, t; }"
        : "=r"(a) : "l"(p));
    return a;
}
__device__ __forceinline__ void cp16(uint32_t saddr, const void* g) {
    asm volatile("cp.async.cg.shared.global [%0], [%1], 16;" :: "r"(saddr), "l"(g));
}
__device__ __forceinline__ void cp_commit() {
    asm volatile("cp.async.commit_group;" ::: "memory");
}
__device__ __forceinline__ void cp_wait0() {
    asm volatile("cp.async.wait_group 0;" ::: "memory");
}
__device__ __forceinline__ void ldsm_x4(uint32_t* r, uint32_t a) {
    asm volatile("ldmatrix.sync.aligned.m8n8.x4.shared.b16 {%0,%1,%2,%3}, [%4];"
                 : "=r"(r[0]), "=r"(r[1]), "=r"(r[2]), "=r"(r[3]) : "r"(a));
}
__device__ __forceinline__ void mma_bf16(float* c, const uint32_t* a, const uint32_t* b) {
    asm volatile(
        "mma.sync.aligned.m16n8k16.row.col.f32.bf16.bf16.f32 "
        "{%0,%1,%2,%3}, {%4,%5,%6,%7}, {%8,%9}, {%0,%1,%2,%3};"
        : "+f"(c[0]), "+f"(c[1]), "+f"(c[2]), "+f"(c[3])
        : "r"(a[0]), "r"(a[1]), "r"(a[2]), "r"(a[3]), "r"(b[0]), "r"(b[1]));
}

// SW128 swizzle: byte_off ^ ((byte_off>>3)&0x70); rows are 128B wide.
#define SWZ(off) ((off) ^ (((off) >> 3) & 0x70))

// ------------- normalization (both matrices) + scalar init -------------
__global__ void normalize_kernel(const float* __restrict__ z1,
                                 const float* __restrict__ z2) {
    int row = blockIdx.x;
    int t = threadIdx.x;  // 128 threads x 4 floats per matrix
    float4 v1 = ((const float4*)(z1 + (size_t)row * DD))[t];
    float4 v2 = ((const float4*)(z2 + (size_t)row * DD))[t];
    float s1 = v1.x * v1.x + v1.y * v1.y + v1.z * v1.z + v1.w * v1.w;
    float s2 = v2.x * v2.x + v2.y * v2.y + v2.z * v2.z + v2.w * v2.w;
#pragma unroll
    for (int o = 16; o; o >>= 1) {
        s1 += __shfl_xor_sync(0xffffffffu, s1, o);
        s2 += __shfl_xor_sync(0xffffffffu, s2, o);
    }
    __shared__ float ws[2][4];
    if ((t & 31) == 0) {
        ws[0][t >> 5] = s1;
        ws[1][t >> 5] = s2;
    }
    __syncthreads();
    float t1 = ws[0][0] + ws[0][1] + ws[0][2] + ws[0][3];
    float t2 = ws[1][0] + ws[1][1] + ws[1][2] + ws[1][3];
    float sc1 = 1.0f / fmaxf(sqrtf(t1), 1e-12f);
    float sc2 = 1.0f / fmaxf(sqrtf(t2), 1e-12f);
    __nv_bfloat162* d1 = (__nv_bfloat162*)(g_zb1 + (size_t)row * DD);
    __nv_bfloat162* d2 = (__nv_bfloat162*)(g_zb2 + (size_t)row * DD);
    d1[t * 2 + 0] = __floats2bfloat162_rn(v1.x * sc1, v1.y * sc1);
    d1[t * 2 + 1] = __floats2bfloat162_rn(v1.z * sc1, v1.w * sc1);
    d2[t * 2 + 0] = __floats2bfloat162_rn(v2.x * sc2, v2.y * sc2);
    d2[t * 2 + 1] = __floats2bfloat162_rn(v2.z * sc2, v2.w * sc2);
    if (t == 0) {
        g_rowsum[row] = 0.0f;
        g_colsum[row] = 0.0f;
        g_diag[row] = 0.0f;
        int e = enc_f(-2.0f);
        g_max1[row] = e;
        g_max2[row] = e;
    }
}

// =====================================================================
// Fused HMMA GEMM, exact 1D grid:
//   t in [0,4096):      mode 0 cross, bi = t>>6, bj = t&63
//   t in [4096,6176):   mode 1 gram z1 (triangle decode)
//   t in [6176,8256):   mode 2 gram z2
// CTA tile 128x128, 4 warps (2x2), warp tile 64x64, BK=64, 8 chunks,
// 2-stage double buffer, SW128 swizzle (no padding): 64KB/CTA -> 3 CTAs/SM.
// =====================================================================
#define ST_A  (128 * 128)                // 16384 (128 rows x 128B)
#define STAGE (2 * ST_A)                 // 32768 (A + B)
#define SMEM_DYN (2 * STAGE)             // 65536
#define NTRI  2080                       // 64*65/2

__global__ __launch_bounds__(128, 3) void gemm_all() {
    int mode, bi, bj;
    {
        int t = blockIdx.x;
        if (t < 4096) {
            mode = 0; bi = t >> 6; bj = t & 63;
        } else {
            int u = t - 4096;
            mode = 1;
            if (u >= NTRI) { mode = 2; u -= NTRI; }
            int b = (int)((sqrtf((float)(8 * u + 1)) - 1.0f) * 0.5f);
            while ((b + 1) * (b + 2) / 2 <= u) b++;
            while (b * (b + 1) / 2 > u) b--;
            bi = b;
            bj = u - b * (b + 1) / 2;
        }
    }
    const bool hasDiag = (bi == bj);

    extern __shared__ __align__(16) char smem[];
    __shared__ int sred[256];            // [0:128) rows, [128:256) cols

    const int tid = threadIdx.x;         // 128
    const int wid = tid >> 5;            // 0..3
    const int lane = tid & 31;
    const int wm = (wid >> 1) * 64;
    const int wn = (wid & 1) * 64;

    const __nv_bfloat16* __restrict__ A = (mode == 2) ? g_zb2 : g_zb1;
    const __nv_bfloat16* __restrict__ B = (mode == 1) ? g_zb1 : g_zb2;

    const size_t arow0 = (size_t)bi * 128;
    const size_t brow0 = (size_t)bj * 128;

    const uint32_t sdyn = smem_u32(smem);

    // loader: per BK=64 chunk, A: 128 rows x 128B (8x16B), B same.
    const int ldrow = tid >> 3;          // 0..15 base (8 iters cover 128)
    const int ldseg = tid & 7;
    auto load_chunk = [&](int kc, int s) {
        uint32_t base = sdyn + s * STAGE;
#pragma unroll
        for (int it = 0; it < 8; it++) {
            int row = ldrow + it * 16;
            uint32_t off = SWZ((uint32_t)row * 128 + ldseg * 16);
            cp16(base + off, A + (arow0 + row) * DD + kc * 64 + ldseg * 8);
            cp16(base + ST_A + off, B + (brow0 + row) * DD + kc * 64 + ldseg * 8);
        }
        cp_commit();
    };

    float acc[4][8][4];
#pragma unroll
    for (int mi = 0; mi < 4; mi++)
#pragma unroll
        for (int ni = 0; ni < 8; ni++)
#pragma unroll
            for (int q = 0; q < 4; q++) acc[mi][ni][q] = 0.0f;

    load_chunk(0, 0);

    // ldmatrix per-lane linear offsets (stage-relative) + constant swizzle mask
    const uint32_t swzMask = (uint32_t)(lane & 7) << 4;
    const uint32_t aLin = (uint32_t)(wm + (lane & 15)) * 128 + (lane >> 4) * 16;
    const uint32_t bLin = ST_A +
        (uint32_t)(wn + (lane & 7) + ((lane >> 4) & 1) * 8) * 128 +
        ((lane >> 3) & 1) * 16;

    for (int i = 0; i < 8; i++) {
        cp_wait0();                      // chunk i arrived
        __syncthreads();                 // + other buffer's old readers done
        if (i + 1 < 8) load_chunk(i + 1, (i + 1) & 1);

        uint32_t stg = sdyn + (i & 1) * STAGE;
#pragma unroll
        for (int k16 = 0; k16 < 4; k16++) {
            uint32_t a[4][4];
#pragma unroll
            for (int mi = 0; mi < 4; mi++)
                ldsm_x4(a[mi], stg + ((aLin + mi * 2048 + k16 * 32) ^ swzMask));
#pragma unroll
            for (int nq = 0; nq < 4; nq++) {
                uint32_t b[4];
                ldsm_x4(b, stg + ((bLin + nq * 2048 + k16 * 32) ^ swzMask));
#pragma unroll
                for (int mi = 0; mi < 4; mi++) {
                    mma_bf16(acc[mi][2 * nq], a[mi], b);
                    mma_bf16(acc[mi][2 * nq + 1], a[mi], b + 2);
                }
            }
        }
    }

    // ---------------- epilogue ----------------
    const int g = lane >> 2;
    const int t4 = lane & 3;

    if (mode == 0) {
        float* sf = (float*)sred;
        sf[tid] = 0.0f;
        sf[128 + tid] = 0.0f;
        __syncthreads();

        float colacc[8][2];
#pragma unroll
        for (int ni = 0; ni < 8; ni++) { colacc[ni][0] = 0.0f; colacc[ni][1] = 0.0f; }

#pragma unroll
        for (int mi = 0; mi < 4; mi++) {
            int gr0 = bi * 128 + wm + mi * 16 + g;
            int gr1 = gr0 + 8;
            float row0 = 0.0f, row1 = 0.0f;
#pragma unroll
            for (int ni = 0; ni < 8; ni++) {
                float l00 = acc[mi][ni][0] * INV_T;
                float l01 = acc[mi][ni][1] * INV_T;
                float l10 = acc[mi][ni][2] * INV_T;
                float l11 = acc[mi][ni][3] * INV_T;
                if (hasDiag) {
                    int gc0 = bj * 128 + wn + ni * 8 + t4 * 2;
                    if (gr0 == gc0)     g_diag[gr0] = l00;
                    if (gr0 == gc0 + 1) g_diag[gr0] = l01;
                    if (gr1 == gc0)     g_diag[gr1] = l10;
                    if (gr1 == gc0 + 1) g_diag[gr1] = l11;
                }
                float e00 = __expf(l00), e01 = __expf(l01);
                float e10 = __expf(l10), e11 = __expf(l11);
                row0 += e00 + e01;
                row1 += e10 + e11;
                colacc[ni][0] += e00 + e10;
                colacc[ni][1] += e01 + e11;
            }
            row0 += __shfl_xor_sync(0xffffffffu, row0, 1);
            row0 += __shfl_xor_sync(0xffffffffu, row0, 2);
            row1 += __shfl_xor_sync(0xffffffffu, row1, 1);
            row1 += __shfl_xor_sync(0xffffffffu, row1, 2);
            if (t4 == 0) {
                atomicAdd(&sf[wm + mi * 16 + g], row0);
                atomicAdd(&sf[wm + mi * 16 + g + 8], row1);
            }
        }
#pragma unroll
        for (int ni = 0; ni < 8; ni++) {
#pragma unroll
            for (int j = 0; j < 2; j++) {
                float v = colacc[ni][j];
                v += __shfl_xor_sync(0xffffffffu, v, 4);
                v += __shfl_xor_sync(0xffffffffu, v, 8);
                v += __shfl_xor_sync(0xffffffffu, v, 16);
                if (lane < 4)
                    atomicAdd(&sf[128 + wn + ni * 8 + (lane & 3) * 2 + j], v);
            }
        }
        __syncthreads();
        atomicAdd(&g_rowsum[bi * 128 + tid], sf[tid]);
        atomicAdd(&g_colsum[bj * 128 + tid], sf[128 + tid]);
    } else {
        int* __restrict__ mx = (mode == 1) ? g_max1 : g_max2;
        const int encneg = enc_f(-2.0f);
        sred[tid] = encneg;
        sred[128 + tid] = encneg;
        __syncthreads();

        float colm[8][2];
#pragma unroll
        for (int ni = 0; ni < 8; ni++) { colm[ni][0] = -2.0f; colm[ni][1] = -2.0f; }

#pragma unroll
        for (int mi = 0; mi < 4; mi++) {
            int gr0 = bi * 128 + wm + mi * 16 + g;
            int gr1 = gr0 + 8;
            float row0 = -2.0f, row1 = -2.0f;
#pragma unroll
            for (int ni = 0; ni < 8; ni++) {
                float v00 = acc[mi][ni][0];
                float v01 = acc[mi][ni][1];
                float v10 = acc[mi][ni][2];
                float v11 = acc[mi][ni][3];
                if (hasDiag) {
                    int gc0 = bj * 128 + wn + ni * 8 + t4 * 2;
                    if (gr0 == gc0)     v00 = -2.0f;
                    if (gr0 == gc0 + 1) v01 = -2.0f;
                    if (gr1 == gc0)     v10 = -2.0f;
                    if (gr1 == gc0 + 1) v11 = -2.0f;
                }
                row0 = fmaxf(row0, fmaxf(v00, v01));
                row1 = fmaxf(row1, fmaxf(v10, v11));
                colm[ni][0] = fmaxf(colm[ni][0], fmaxf(v00, v10));
                colm[ni][1] = fmaxf(colm[ni][1], fmaxf(v01, v11));
            }
            row0 = fmaxf(row0, __shfl_xor_sync(0xffffffffu, row0, 1));
            row0 = fmaxf(row0, __shfl_xor_sync(0xffffffffu, row0, 2));
            row1 = fmaxf(row1, __shfl_xor_sync(0xffffffffu, row1, 1));
            row1 = fmaxf(row1, __shfl_xor_sync(0xffffffffu, row1, 2));
            if (t4 == 0) {
                atomicMax(&sred[wm + mi * 16 + g], enc_f(row0));
                atomicMax(&sred[wm + mi * 16 + g + 8], enc_f(row1));
            }
        }
#pragma unroll
        for (int ni = 0; ni < 8; ni++) {
#pragma unroll
            for (int j = 0; j < 2; j++) {
                float v = colm[ni][j];
                v = fmaxf(v, __shfl_xor_sync(0xffffffffu, v, 4));
                v = fmaxf(v, __shfl_xor_sync(0xffffffffu, v, 8));
                v = fmaxf(v, __shfl_xor_sync(0xffffffffu, v, 16));
                if (lane < 4)
                    atomicMax(&sred[128 + wn + ni * 8 + (lane & 3) * 2 + j], enc_f(v));
            }
        }
        __syncthreads();
        atomicMax(&mx[bi * 128 + tid], sred[tid]);
        atomicMax(&mx[bj * 128 + tid], sred[128 + tid]);
    }
}

// ------------------- final scalar reduction (1024 threads) -------------------
__global__ void finalize_kernel(float* __restrict__ out) {
    const int t = threadIdx.x;  // 1024
    float s12 = 0.0f, s21 = 0.0f, k1 = 0.0f, k2 = 0.0f;
#pragma unroll
    for (int it = 0; it < NN / 1024; it++) {
        int i = t + it * 1024;
        float d = g_diag[i];
        s12 += __logf(g_rowsum[i]) - d;
        s21 += __logf(g_colsum[i]) - d;
        float m1 = dec_f(g_max1[i]);
        float m2 = dec_f(g_max2[i]);
        float d1 = sqrtf(fmaxf(2.0f - 2.0f * m1, 0.0f));
        float d2 = sqrtf(fmaxf(2.0f - 2.0f * m2, 0.0f));
        k1 += __logf(d1 + EPS_KOLEO);
        k2 += __logf(d2 + EPS_KOLEO);
    }
    float vals[4] = {s12, s21, k1, k2};
    __shared__ float sh[4][32];
#pragma unroll
    for (int q = 0; q < 4; q++) {
        float v = vals[q];
#pragma unroll
        for (int o = 16; o; o >>= 1) v += __shfl_xor_sync(0xffffffffu, v, o);
        if ((t & 31) == 0) sh[q][t >> 5] = v;
    }
    __syncthreads();
    if (t < 32) {
        float r[4];
#pragma unroll
        for (int q = 0; q < 4; q++) {
            float v = sh[q][t];
#pragma unroll
            for (int o = 16; o; o >>= 1) v += __shfl_xor_sync(0xffffffffu, v, o);
            r[q] = v;
        }
        if (t == 0) {
            float contrast = (r[0] + r[1]) / (2.0f * NN);
            float koleo = -(r[2] + r[3]) / (2.0f * NN);
            out[0] = contrast + 0.1f * koleo;
        }
    }
}

// ------------------- launch -------------------
extern "C" void kernel_launch(void* const* d_in, const int* in_sizes, int n_in,
                              void* d_out, int out_size) {
    const float* z1 = (const float*)d_in[0];
    const float* z2 = (const float*)d_in[1];
    float* out = (float*)d_out;

    cudaFuncSetAttribute(gemm_all, cudaFuncAttributeMaxDynamicSharedMemorySize,
                         SMEM_DYN);

    normalize_kernel<<<NN, 128>>>(z1, z2);
    gemm_all<<<4096 + 2 * NTRI, 128, SMEM_DYN>>>();
    finalize_kernel<<<1, 1024>>>(out);
}

// round 13
// speedup vs baseline: 1.9086x; 1.2676x over previous
#include <cuda_runtime.h>
#include <cuda_bf16.h>
#include <cstdint>

#define NN 8192
#define DD 512
#define INV_T 25.0f
#define EPS_KOLEO 1e-9f

// ------------------- device scratch -------------------
__device__ __nv_bfloat16 g_zb1[NN * DD];
__device__ __nv_bfloat16 g_zb2[NN * DD];
__device__ float g_rowsum[NN];
__device__ float g_colsum[NN];
__device__ float g_diag[NN];
__device__ int   g_max1[NN];
__device__ int   g_max2[NN];
__device__ float4 g_part[16];

// ------------------- helpers -------------------
__device__ __forceinline__ int enc_f(float f) {
    int i = __float_as_int(f);
    return i >= 0 ? i : i ^ 0x7FFFFFFF;
}
__device__ __forceinline__ float dec_f(int i) {
    return __int_as_float(i >= 0 ? i : i ^ 0x7FFFFFFF);
}
__device__ __forceinline__ uint32_t smem_u32(const void* p) {
    uint32_t a;
    asm("{ .reg .u64 t; cvta.to.shared.u64 t, %1; cvt.u32.u64 %0, t; }"
        : "=r"(a) : "l"(p));
    return a;
}
__device__ __forceinline__ void cp16(uint32_t saddr, const void* g) {
    asm volatile("cp.async.cg.shared.global [%0], [%1], 16;" :: "r"(saddr), "l"(g));
}
__device__ __forceinline__ void cp_commit() {
    asm volatile("cp.async.commit_group;" ::: "memory");
}
__device__ __forceinline__ void cp_wait1() {
    asm volatile("cp.async.wait_group 1;" ::: "memory");
}
__device__ __forceinline__ void cp_wait0() {
    asm volatile("cp.async.wait_group 0;" ::: "memory");
}
__device__ __forceinline__ void ldsm_x4(uint32_t* r, uint32_t a) {
    asm volatile("ldmatrix.sync.aligned.m8n8.x4.shared.b16 {%0,%1,%2,%3}, [%4];"
                 : "=r"(r[0]), "=r"(r[1]), "=r"(r[2]), "=r"(r[3]) : "r"(a));
}
__device__ __forceinline__ void mma_bf16(float* c, const uint32_t* a, const uint32_t* b) {
    asm volatile(
        "mma.sync.aligned.m16n8k16.row.col.f32.bf16.bf16.f32 "
        "{%0,%1,%2,%3}, {%4,%5,%6,%7}, {%8,%9}, {%0,%1,%2,%3};"
        : "+f"(c[0]), "+f"(c[1]), "+f"(c[2]), "+f"(c[3])
        : "r"(a[0]), "r"(a[1]), "r"(a[2]), "r"(a[3]), "r"(b[0]), "r"(b[1]));
}

// SW128 swizzle: byte_off ^ ((byte_off>>3)&0x70); rows are 128B wide.
#define SWZ(off) ((off) ^ (((off) >> 3) & 0x70))

// ------------- normalization (both matrices) + scalar init -------------
__global__ void normalize_kernel(const float* __restrict__ z1,
                                 const float* __restrict__ z2) {
    int row = blockIdx.x;
    int t = threadIdx.x;  // 128 threads x 4 floats per matrix
    float4 v1 = ((const float4*)(z1 + (size_t)row * DD))[t];
    float4 v2 = ((const float4*)(z2 + (size_t)row * DD))[t];
    float s1 = v1.x * v1.x + v1.y * v1.y + v1.z * v1.z + v1.w * v1.w;
    float s2 = v2.x * v2.x + v2.y * v2.y + v2.z * v2.z + v2.w * v2.w;
#pragma unroll
    for (int o = 16; o; o >>= 1) {
        s1 += __shfl_xor_sync(0xffffffffu, s1, o);
        s2 += __shfl_xor_sync(0xffffffffu, s2, o);
    }
    __shared__ float ws[2][4];
    if ((t & 31) == 0) {
        ws[0][t >> 5] = s1;
        ws[1][t >> 5] = s2;
    }
    __syncthreads();
    float t1 = ws[0][0] + ws[0][1] + ws[0][2] + ws[0][3];
    float t2 = ws[1][0] + ws[1][1] + ws[1][2] + ws[1][3];
    float sc1 = 1.0f / fmaxf(sqrtf(t1), 1e-12f);
    float sc2 = 1.0f / fmaxf(sqrtf(t2), 1e-12f);
    __nv_bfloat162* d1 = (__nv_bfloat162*)(g_zb1 + (size_t)row * DD);
    __nv_bfloat162* d2 = (__nv_bfloat162*)(g_zb2 + (size_t)row * DD);
    d1[t * 2 + 0] = __floats2bfloat162_rn(v1.x * sc1, v1.y * sc1);
    d1[t * 2 + 1] = __floats2bfloat162_rn(v1.z * sc1, v1.w * sc1);
    d2[t * 2 + 0] = __floats2bfloat162_rn(v2.x * sc2, v2.y * sc2);
    d2[t * 2 + 1] = __floats2bfloat162_rn(v2.z * sc2, v2.w * sc2);
    if (t == 0) {
        g_rowsum[row] = 0.0f;
        g_colsum[row] = 0.0f;
        g_diag[row] = 0.0f;
        int e = enc_f(-2.0f);
        g_max1[row] = e;
        g_max2[row] = e;
    }
}

// =====================================================================
// Fused HMMA GEMM, exact 1D grid:
//   t in [0,4096):      mode 0 cross, bi = t>>6, bj = t&63
//   t in [4096,6176):   mode 1 gram z1 (triangle decode)
//   t in [6176,8256):   mode 2 gram z2
// CTA tile 128x128, 4 warps (2x2), warp tile 64x64, BK=64, 8 chunks,
// 3-stage ring (depth-2 prefetch, wait_group 1 steady state),
// SW128 swizzle: 96KB/CTA -> 2 CTAs/SM (192KB of 228KB).
// =====================================================================
#define ST_A  (128 * 128)                // 16384 (128 rows x 128B)
#define STAGE (2 * ST_A)                 // 32768 (A + B)
#define SMEM_DYN (3 * STAGE)             // 98304
#define NTRI  2080                       // 64*65/2

__global__ __launch_bounds__(128, 2) void gemm_all() {
    int mode, bi, bj;
    {
        int t = blockIdx.x;
        if (t < 4096) {
            mode = 0; bi = t >> 6; bj = t & 63;
        } else {
            int u = t - 4096;
            mode = 1;
            if (u >= NTRI) { mode = 2; u -= NTRI; }
            int b = (int)((sqrtf((float)(8 * u + 1)) - 1.0f) * 0.5f);
            while ((b + 1) * (b + 2) / 2 <= u) b++;
            while (b * (b + 1) / 2 > u) b--;
            bi = b;
            bj = u - b * (b + 1) / 2;
        }
    }
    const bool hasDiag = (bi == bj);

    extern __shared__ __align__(16) char smem[];
    __shared__ int sred[256];            // [0:128) rows, [128:256) cols

    const int tid = threadIdx.x;         // 128
    const int wid = tid >> 5;            // 0..3
    const int lane = tid & 31;
    const int wm = (wid >> 1) * 64;
    const int wn = (wid & 1) * 64;

    const __nv_bfloat16* __restrict__ A = (mode == 2) ? g_zb2 : g_zb1;
    const __nv_bfloat16* __restrict__ B = (mode == 1) ? g_zb1 : g_zb2;

    const size_t arow0 = (size_t)bi * 128;
    const size_t brow0 = (size_t)bj * 128;

    const uint32_t sdyn = smem_u32(smem);

    // loader: per BK=64 chunk, A: 128 rows x 128B (8x16B), B same.
    const int ldrow = tid >> 3;          // 0..15 base (8 iters cover 128)
    const int ldseg = tid & 7;
    auto load_chunk = [&](int kc, int s) {
        uint32_t base = sdyn + s * STAGE;
#pragma unroll
        for (int it = 0; it < 8; it++) {
            int row = ldrow + it * 16;
            uint32_t off = SWZ((uint32_t)row * 128 + ldseg * 16);
            cp16(base + off, A + (arow0 + row) * DD + kc * 64 + ldseg * 8);
            cp16(base + ST_A + off, B + (brow0 + row) * DD + kc * 64 + ldseg * 8);
        }
        cp_commit();
    };

    float acc[4][8][4];
#pragma unroll
    for (int mi = 0; mi < 4; mi++)
#pragma unroll
        for (int ni = 0; ni < 8; ni++)
#pragma unroll
            for (int q = 0; q < 4; q++) acc[mi][ni][q] = 0.0f;

    load_chunk(0, 0);
    load_chunk(1, 1);

    // ldmatrix per-lane linear offsets (stage-relative) + constant swizzle mask
    const uint32_t swzMask = (uint32_t)(lane & 7) << 4;
    const uint32_t aLin = (uint32_t)(wm + (lane & 15)) * 128 + (lane >> 4) * 16;
    const uint32_t bLin = ST_A +
        (uint32_t)(wn + (lane & 7) + ((lane >> 4) & 1) * 8) * 128 +
        ((lane >> 3) & 1) * 16;

    int s = 0;
    for (int i = 0; i < 8; i++) {
        if (i < 7) cp_wait1(); else cp_wait0();   // chunk i arrived
        __syncthreads();                          // stage (i+2)%3's readers done
        if (i + 2 < 8) {
            int sn = s + 2; if (sn >= 3) sn -= 3;
            load_chunk(i + 2, sn);
        }

        uint32_t stg = sdyn + s * STAGE;
#pragma unroll
        for (int k16 = 0; k16 < 4; k16++) {
            uint32_t a[4][4];
#pragma unroll
            for (int mi = 0; mi < 4; mi++)
                ldsm_x4(a[mi], stg + ((aLin + mi * 2048 + k16 * 32) ^ swzMask));
#pragma unroll
            for (int nq = 0; nq < 4; nq++) {
                uint32_t b[4];
                ldsm_x4(b, stg + ((bLin + nq * 2048 + k16 * 32) ^ swzMask));
#pragma unroll
                for (int mi = 0; mi < 4; mi++) {
                    mma_bf16(acc[mi][2 * nq], a[mi], b);
                    mma_bf16(acc[mi][2 * nq + 1], a[mi], b + 2);
                }
            }
        }
        s++; if (s >= 3) s -= 3;
    }

    // ---------------- epilogue ----------------
    const int g = lane >> 2;
    const int t4 = lane & 3;

    if (mode == 0) {
        float* sf = (float*)sred;
        sf[tid] = 0.0f;
        sf[128 + tid] = 0.0f;
        __syncthreads();

        float colacc[8][2];
#pragma unroll
        for (int ni = 0; ni < 8; ni++) { colacc[ni][0] = 0.0f; colacc[ni][1] = 0.0f; }

#pragma unroll
        for (int mi = 0; mi < 4; mi++) {
            int gr0 = bi * 128 + wm + mi * 16 + g;
            int gr1 = gr0 + 8;
            float row0 = 0.0f, row1 = 0.0f;
#pragma unroll
            for (int ni = 0; ni < 8; ni++) {
                float l00 = acc[mi][ni][0] * INV_T;
                float l01 = acc[mi][ni][1] * INV_T;
                float l10 = acc[mi][ni][2] * INV_T;
                float l11 = acc[mi][ni][3] * INV_T;
                if (hasDiag) {
                    int gc0 = bj * 128 + wn + ni * 8 + t4 * 2;
                    if (gr0 == gc0)     g_diag[gr0] = l00;
                    if (gr0 == gc0 + 1) g_diag[gr0] = l01;
                    if (gr1 == gc0)     g_diag[gr1] = l10;
                    if (gr1 == gc0 + 1) g_diag[gr1] = l11;
                }
                float e00 = __expf(l00), e01 = __expf(l01);
                float e10 = __expf(l10), e11 = __expf(l11);
                row0 += e00 + e01;
                row1 += e10 + e11;
                colacc[ni][0] += e00 + e10;
                colacc[ni][1] += e01 + e11;
            }
            row0 += __shfl_xor_sync(0xffffffffu, row0, 1);
            row0 += __shfl_xor_sync(0xffffffffu, row0, 2);
            row1 += __shfl_xor_sync(0xffffffffu, row1, 1);
            row1 += __shfl_xor_sync(0xffffffffu, row1, 2);
            if (t4 == 0) {
                atomicAdd(&sf[wm + mi * 16 + g], row0);
                atomicAdd(&sf[wm + mi * 16 + g + 8], row1);
            }
        }
#pragma unroll
        for (int ni = 0; ni < 8; ni++) {
#pragma unroll
            for (int j = 0; j < 2; j++) {
                float v = colacc[ni][j];
                v += __shfl_xor_sync(0xffffffffu, v, 4);
                v += __shfl_xor_sync(0xffffffffu, v, 8);
                v += __shfl_xor_sync(0xffffffffu, v, 16);
                if (lane < 4)
                    atomicAdd(&sf[128 + wn + ni * 8 + (lane & 3) * 2 + j], v);
            }
        }
        __syncthreads();
        atomicAdd(&g_rowsum[bi * 128 + tid], sf[tid]);
        atomicAdd(&g_colsum[bj * 128 + tid], sf[128 + tid]);
    } else {
        int* __restrict__ mx = (mode == 1) ? g_max1 : g_max2;
        const int encneg = enc_f(-2.0f);
        sred[tid] = encneg;
        sred[128 + tid] = encneg;
        __syncthreads();

        float colm[8][2];
#pragma unroll
        for (int ni = 0; ni < 8; ni++) { colm[ni][0] = -2.0f; colm[ni][1] = -2.0f; }

#pragma unroll
        for (int mi = 0; mi < 4; mi++) {
            int gr0 = bi * 128 + wm + mi * 16 + g;
            int gr1 = gr0 + 8;
            float row0 = -2.0f, row1 = -2.0f;
#pragma unroll
            for (int ni = 0; ni < 8; ni++) {
                float v00 = acc[mi][ni][0];
                float v01 = acc[mi][ni][1];
                float v10 = acc[mi][ni][2];
                float v11 = acc[mi][ni][3];
                if (hasDiag) {
                    int gc0 = bj * 128 + wn + ni * 8 + t4 * 2;
                    if (gr0 == gc0)     v00 = -2.0f;
                    if (gr0 == gc0 + 1) v01 = -2.0f;
                    if (gr1 == gc0)     v10 = -2.0f;
                    if (gr1 == gc0 + 1) v11 = -2.0f;
                }
                row0 = fmaxf(row0, fmaxf(v00, v01));
                row1 = fmaxf(row1, fmaxf(v10, v11));
                colm[ni][0] = fmaxf(colm[ni][0], fmaxf(v00, v10));
                colm[ni][1] = fmaxf(colm[ni][1], fmaxf(v01, v11));
            }
            row0 = fmaxf(row0, __shfl_xor_sync(0xffffffffu, row0, 1));
            row0 = fmaxf(row0, __shfl_xor_sync(0xffffffffu, row0, 2));
            row1 = fmaxf(row1, __shfl_xor_sync(0xffffffffu, row1, 1));
            row1 = fmaxf(row1, __shfl_xor_sync(0xffffffffu, row1, 2));
            if (t4 == 0) {
                atomicMax(&sred[wm + mi * 16 + g], enc_f(row0));
                atomicMax(&sred[wm + mi * 16 + g + 8], enc_f(row1));
            }
        }
#pragma unroll
        for (int ni = 0; ni < 8; ni++) {
#pragma unroll
            for (int j = 0; j < 2; j++) {
                float v = colm[ni][j];
                v = fmaxf(v, __shfl_xor_sync(0xffffffffu, v, 4));
                v = fmaxf(v, __shfl_xor_sync(0xffffffffu, v, 8));
                v = fmaxf(v, __shfl_xor_sync(0xffffffffu, v, 16));
                if (lane < 4)
                    atomicMax(&sred[128 + wn + ni * 8 + (lane & 3) * 2 + j], enc_f(v));
            }
        }
        __syncthreads();
        atomicMax(&mx[bi * 128 + tid], sred[tid]);
        atomicMax(&mx[bj * 128 + tid], sred[128 + tid]);
    }
}

// ------------------- finalize: 16-block partials + tiny reduce -------------------
__global__ void finalize_partial() {
    int i = blockIdx.x * 512 + threadIdx.x;   // one row per thread
    float d = g_diag[i];
    float s12 = __logf(g_rowsum[i]) - d;
    float s21 = __logf(g_colsum[i]) - d;
    float m1 = dec_f(g_max1[i]);
    float m2 = dec_f(g_max2[i]);
    float k1 = __logf(sqrtf(fmaxf(2.0f - 2.0f * m1, 0.0f)) + EPS_KOLEO);
    float k2 = __logf(sqrtf(fmaxf(2.0f - 2.0f * m2, 0.0f)) + EPS_KOLEO);
    float vals[4] = {s12, s21, k1, k2};
    __shared__ float sh[4][16];
#pragma unroll
    for (int q = 0; q < 4; q++) {
        float v = vals[q];
#pragma unroll
        for (int o = 16; o; o >>= 1) v += __shfl_xor_sync(0xffffffffu, v, o);
        if ((threadIdx.x & 31) == 0) sh[q][threadIdx.x >> 5] = v;
    }
    __syncthreads();
    if (threadIdx.x < 16) {
        float v0 = sh[0][threadIdx.x], v1 = sh[1][threadIdx.x];
        float v2 = sh[2][threadIdx.x], v3 = sh[3][threadIdx.x];
#pragma unroll
        for (int o = 8; o; o >>= 1) {
            v0 += __shfl_xor_sync(0xffffu, v0, o);
            v1 += __shfl_xor_sync(0xffffu, v1, o);
            v2 += __shfl_xor_sync(0xffffu, v2, o);
            v3 += __shfl_xor_sync(0xffffu, v3, o);
        }
        if (threadIdx.x == 0) g_part[blockIdx.x] = make_float4(v0, v1, v2, v3);
    }
}

__global__ void finalize_final(float* __restrict__ out) {
    int t = threadIdx.x;   // 16 active
    float4 p = (t < 16) ? g_part[t] : make_float4(0.f, 0.f, 0.f, 0.f);
#pragma unroll
    for (int o = 8; o; o >>= 1) {
        p.x += __shfl_xor_sync(0xffffffffu, p.x, o);
        p.y += __shfl_xor_sync(0xffffffffu, p.y, o);
        p.z += __shfl_xor_sync(0xffffffffu, p.z, o);
        p.w += __shfl_xor_sync(0xffffffffu, p.w, o);
    }
    if (t == 0) {
        float contrast = (p.x + p.y) / (2.0f * NN);
        float koleo = -(p.z + p.w) / (2.0f * NN);
        out[0] = contrast + 0.1f * koleo;
    }
}

// ------------------- launch -------------------
extern "C" void kernel_launch(void* const* d_in, const int* in_sizes, int n_in,
                              void* d_out, int out_size) {
    const float* z1 = (const float*)d_in[0];
    const float* z2 = (const float*)d_in[1];
    float* out = (float*)d_out;

    cudaFuncSetAttribute(gemm_all, cudaFuncAttributeMaxDynamicSharedMemorySize,
                         SMEM_DYN);

    normalize_kernel<<<NN, 128>>>(z1, z2);
    gemm_all<<<4096 + 2 * NTRI, 128, SMEM_DYN>>>();
    finalize_partial<<<16, 512>>>();
    finalize_final<<<1, 32>>>(out);
}